// round 17
// baseline (speedup 1.0000x reference)
#include <cuda_runtime.h>
#include <cuda_bf16.h>
#include <cstdint>

// Problem constants: B=32, T=1024, F=4, C=256, S=256, MAX_DUR=8 (durations <= 7)
#define BQ 32
#define TQ 1024
#define FQ 4
#define CQ 256
#define SQ 256
#define ROW_VEC 256        // one frame row [F=4][C=256] = 1024 floats = 256 float4
#define ROW_BYTES 4096

// ---------------------------------------------------------------------------
// Fused kernel, TMA (cp.async.bulk) load path instead of LDG.
// Grid: 8192 blocks = one per (batch, segment), 256 threads.
// Phase 1: in-block inclusive scan of the batch's 256 durations (as before).
// Phase 2: ONE cp.async.bulk.shared::cta of cnt*4096 bytes (the segment's
// contiguous frame rows) tracked by an mbarrier; then LDS.128 accumulate
// (thread tid = float4 column of the row) and the proven smem freq-reduce +
// coalesced float4 store. The bulk copy replaces 8 predicated LDG.128 per
// thread with a single async-proxy transfer per CTA — bypassing the per-SM
// LDG/L1tex path that all seven previous variants plateaued on.
//
// Dtype: reference declares int64 but JAX w/o x64 downcasts to int32; detect
// on device via high words (all zero <=> int64; P(false pos)=8^-32).
// ---------------------------------------------------------------------------
__global__ __launch_bounds__(256, 6) void fused_kernel(const float* __restrict__ e,
                                                       const int* __restrict__ dur_raw,
                                                       float4* __restrict__ out4) {
    __shared__ int sh_cum[SQ];
    __shared__ int warp_tot[8];
    __shared__ int s_is64;
    __shared__ alignas(8) uint64_t mbar;
    __shared__ alignas(128) float4 data[7 * 256];   // up to 7 frame rows (28 KB)
    __shared__ float4 shred[CQ];                    // 4 KB reduce buffer

    const int blk = blockIdx.x;
    const int b   = blk >> 8;          // batch
    const int s   = blk & (SQ - 1);    // segment
    const int tid = threadIdx.x;
    const int lane = tid & 31;
    const int w    = tid >> 5;

    // --- mbarrier init (single thread) ---
    uint32_t mbar_addr;
    {
        uint64_t tmp;
        asm("cvta.to.shared.u64 %0, %1;" : "=l"(tmp) : "l"(&mbar));
        mbar_addr = (uint32_t)tmp;
    }
    if (tid == 0) {
        asm volatile("mbarrier.init.shared.b64 [%0], %1;" :: "r"(mbar_addr), "r"(1) : "memory");
    }

    // --- dtype probe (first 32 candidate int64 high words of whole array) ---
    if (tid < 32) {
        int v = dur_raw[2 * tid + 1];
        unsigned m = __ballot_sync(0xffffffffu, v != 0);
        if (tid == 0) s_is64 = (m == 0u) ? 1 : 0;
    }
    __syncthreads();   // also publishes mbarrier init to the block

    // --- phase 1: inclusive scan of batch b's durations (tid = phone id) ---
    int d = s_is64 ? dur_raw[(b * SQ + tid) * 2]    // low word of LE int64
                   : dur_raw[b * SQ + tid];

    int x = d;
    #pragma unroll
    for (int off = 1; off < 32; off <<= 1) {
        int y = __shfl_up_sync(0xffffffffu, x, off);
        if (lane >= off) x += y;
    }
    if (lane == 31) warp_tot[w] = x;
    __syncthreads();

    int base = 0;
    #pragma unroll
    for (int i = 0; i < 8; ++i)
        if (i < w) base += warp_tot[i];

    sh_cum[tid] = base + x;
    __syncthreads();

    // --- phase 2: TMA bulk load of this segment's frames, then reduce ---
    const int incl  = sh_cum[s];
    const int excl  = (s == 0) ? 0 : sh_cum[s - 1];
    const int start = min(excl, TQ);
    const int cnt   = min(incl, TQ) - start;
    const unsigned bytes = (unsigned)cnt * ROW_BYTES;

    if (tid == 0) {
        // expect_tx (also the single arrival); completes immediately if bytes==0
        asm volatile("mbarrier.arrive.expect_tx.shared.b64 _, [%0], %1;"
                     :: "r"(mbar_addr), "r"(bytes) : "memory");
        if (bytes > 0) {
            uint32_t dst;
            {
                uint64_t tmp;
                asm("cvta.to.shared.u64 %0, %1;" : "=l"(tmp) : "l"(&data[0]));
                dst = (uint32_t)tmp;
            }
            const float* src = e + (size_t)(b * TQ + start) * (FQ * CQ);
            asm volatile(
                "cp.async.bulk.shared::cta.global.mbarrier::complete_tx::bytes "
                "[%0], [%1], %2, [%3];"
                :: "r"(dst), "l"(src), "r"(bytes), "r"(mbar_addr) : "memory");
        }
    }

    // wait (acquire) for the bulk copy
    {
        uint32_t done;
        asm volatile(
            "{\n\t"
            ".reg .pred p;\n\t"
            "mbarrier.try_wait.parity.acquire.cta.shared::cta.b64 p, [%1], %2;\n\t"
            "selp.b32 %0, 1, 0, p;\n\t"
            "}"
            : "=r"(done) : "r"(mbar_addr), "r"(0) : "memory");
        if (!done) {
            asm volatile(
                "{\n\t"
                ".reg .pred P1;\n\t"
                "WAIT_LOOP_%=:\n\t"
                "mbarrier.try_wait.parity.acquire.cta.shared::cta.b64 P1, [%0], %1, 0x989680;\n\t"
                "@P1 bra.uni WAIT_DONE_%=;\n\t"
                "bra.uni WAIT_LOOP_%=;\n\t"
                "WAIT_DONE_%=:\n\t"
                "}"
                :: "r"(mbar_addr), "r"(0) : "memory");
        }
    }

    // accumulate from smem: thread tid = float4 column of the frame row
    float4 acc = make_float4(0.f, 0.f, 0.f, 0.f);
    #pragma unroll
    for (int t = 0; t < 7; ++t) {
        if (t < cnt) {
            float4 v = data[t * ROW_VEC + tid];
            acc.x += v.x; acc.y += v.y; acc.z += v.z; acc.w += v.w;
        }
    }
    shred[tid] = acc;
    __syncthreads();

    if (tid < 64) {
        float4 a  = shred[tid];
        float4 b1 = shred[tid + 64];
        float4 b2 = shred[tid + 128];
        float4 b3 = shred[tid + 192];
        const float inv = (cnt > 0) ? 1.0f / (float)(cnt * FQ) : 0.0f;
        float4 r;
        r.x = ((a.x + b1.x) + (b2.x + b3.x)) * inv;
        r.y = ((a.y + b1.y) + (b2.y + b3.y)) * inv;
        r.z = ((a.z + b1.z) + (b2.z + b3.z)) * inv;
        r.w = ((a.w + b1.w) + (b2.w + b3.w)) * inv;
        __stcs(out4 + (size_t)blk * 64 + tid, r);
    }
}

extern "C" void kernel_launch(void* const* d_in, const int* in_sizes, int n_in,
                              void* d_out, int out_size) {
    const float* e_src = (const float*)d_in[0];   // [B, T, F, C] float32
    const int*   d_src = (const int*)d_in[1];     // [B, S] int64-or-int32 (detected)
    float4* out = (float4*)d_out;                 // [B, S, C] float32

    fused_kernel<<<BQ * SQ, 256>>>(e_src, d_src, out);
}